// round 10
// baseline (speedup 1.0000x reference)
#include <cuda_runtime.h>

// out[b,i,j,d] = x[b,i,j,d] + W[d, bin] + bias[d],  bin = clip(i-j,-31,31)+31
// B=2, L=512, D=128. x/out: 256 MB each (fp32). Pure HBM stream.
//
// Inputs (metadata order): d_in[0]=x (f32), d_in[1]=idx (i64, unused),
//                          d_in[2]=W (f32 [128,63]), d_in[3]=b (f32 [128])
//
// R9: SINGLE kernel (the 2nd graph node costs ~8-10us; R4 showed gap==0 for
// one node). Blocks 0..62 build the 32KB table once (cooperative one-shot,
// release via threadfence+atomic); all blocks front-batch their x DRAM loads
// BEFORE the acquire-spin so the HBM stream starts immediately. A done-counter
// resets the flags at kernel end -> every graph replay is identical.

#define L_DIM   512
#define D_DIM   128
#define NBINS   63
#define TOTAL_F4 (2 * L_DIM * L_DIM * (D_DIM / 4))   // 16,777,216
#define VPT 4
#define TPB 256
#define GRID (TOTAL_F4 / (TPB * VPT))                 // 16384

// relemb[bin][d] = W[d][bin] + b[d]  (63*128 floats = 32 KB)
__device__ float4 g_relemb[NBINS * (D_DIM / 4)];
__device__ int    g_flag = 0;   // prep-done counter (0..63), reset each run
__device__ int    g_done = 0;   // block-done counter, reset each run

__device__ __forceinline__ int acquire_load(const int* p) {
    int v;
    asm volatile("ld.acquire.gpu.global.b32 %0, [%1];" : "=r"(v) : "l"(p) : "memory");
    return v;
}

__global__ __launch_bounds__(TPB)
void add_rel_fused_kernel(const float4* __restrict__ x,
                          float4* __restrict__ out,
                          const float* __restrict__ W,
                          const float* __restrict__ bias) {
    const int tid  = threadIdx.x;
    const int base = blockIdx.x * (TPB * VPT) + tid;

    // 1) Front-batch the 4 independent DRAM loads (MLP=4). These never
    //    depend on the table, so the 512MB stream starts immediately.
    float4 xv[VPT];
    #pragma unroll
    for (int k = 0; k < VPT; k++)
        xv[k] = __ldcs(&x[base + k * TPB]);

    // 2) Blocks 0..62 build the table (coalesced W reads: block b covers
    //    W[b*128 .. b*128+127]). ~1us total, inside wave 1.
    if (blockIdx.x < NBINS) {
        if (tid < 128) {
            unsigned t  = blockIdx.x * 128u + tid;        // 0..8063
            unsigned d  = t / NBINS;                      // W is [128,63] row-major
            unsigned bn = t - d * NBINS;
            reinterpret_cast<float*>(g_relemb)[bn * D_DIM + d] = W[t] + bias[d];
            __threadfence();                              // release my writes
        }
        __syncthreads();
        if (tid == 0) atomicAdd(&g_flag, 1);
    }

    // 3) Acquire-spin until all 63 prep blocks signaled (hidden under the
    //    in-flight DRAM loads for wave 1; one poll for later waves).
    if (tid == 0) {
        while (acquire_load(&g_flag) < NBINS) __nanosleep(64);
    }
    __syncthreads();

    // 4) Main stream work: bin is warp-uniform; table read is a coalesced
    //    L1/L2 hit.
    #pragma unroll
    for (int k = 0; k < VPT; k++) {
        int g   = base + k * TPB;
        int d4  = g & 31;
        int row = g >> 5;                         // b*L*L + i*L + j
        int j   = row & (L_DIM - 1);
        int i   = (row >> 9) & (L_DIM - 1);
        int rel = i - j;
        rel = max(-(NBINS / 2), min(NBINS / 2, rel));
        int bin = rel + NBINS / 2;                // 0..62
        float4 rv = g_relemb[bin * 32 + d4];
        float4 ov;
        ov.x = xv[k].x + rv.x;
        ov.y = xv[k].y + rv.y;
        ov.z = xv[k].z + rv.z;
        ov.w = xv[k].w + rv.w;
        __stcs(&out[base + k * TPB], ov);
    }

    // 5) Self-reset so every graph replay starts from flag=0/done=0.
    //    Last-finishing block resets; all blocks have passed the spin by
    //    the time done == GRID-1, so no waiter can observe the reset.
    __syncthreads();
    if (tid == 0) {
        int d = atomicAdd(&g_done, 1);
        if (d == GRID - 1) {
            g_flag = 0;
            g_done = 0;
            __threadfence();
        }
    }
}

extern "C" void kernel_launch(void* const* d_in, const int* in_sizes, int n_in,
                              void* d_out, int out_size) {
    const float* x    = (const float*)d_in[0];
    const float* W    = (const float*)d_in[2];
    const float* bias = (const float*)d_in[3];
    float* out        = (float*)d_out;

    add_rel_fused_kernel<<<GRID, TPB>>>(
        (const float4*)x, (float4*)out, W, bias);
}

// round 11
// speedup vs baseline: 1.0076x; 1.0076x over previous
#include <cuda_runtime.h>

// out[b,i,j,d] = x[b,i,j,d] + W[d, bin] + bias[d],  bin = clip(i-j,-31,31)+31
// B=2, L=512, D=128. x/out: 256 MB each (fp32). Pure HBM stream.
//
// Inputs (metadata order): d_in[0]=x (f32), d_in[1]=idx (i64, unused),
//                          d_in[2]=W (f32 [128,63]), d_in[3]=b (f32 [128])
//
// R10: single kernel (single graph node: ~6us cheaper than two nodes).
// Fix vs R9: prep blocks build the table BEFORE issuing their own stream
// loads, so the 32KB of W reads don't queue behind the wave-1 DRAM flood
// (that queueing caused a multi-us startup bubble: DRAM 82%->75%).
// One release-fence per prep block instead of per thread.

#define L_DIM   512
#define D_DIM   128
#define NBINS   63
#define TOTAL_F4 (2 * L_DIM * L_DIM * (D_DIM / 4))   // 16,777,216
#define VPT 4
#define TPB 256
#define GRID (TOTAL_F4 / (TPB * VPT))                 // 16384

// relemb[bin][d] = W[d][bin] + b[d]  (63*128 floats = 32 KB)
__device__ float4 g_relemb[NBINS * (D_DIM / 4)];
__device__ int    g_flag = 0;   // prep-done counter (0..63), reset each run
__device__ int    g_done = 0;   // block-done counter, reset each run

__device__ __forceinline__ int acquire_load(const int* p) {
    int v;
    asm volatile("ld.acquire.gpu.global.b32 %0, [%1];" : "=r"(v) : "l"(p) : "memory");
    return v;
}

__global__ __launch_bounds__(TPB)
void add_rel_fused_kernel(const float4* __restrict__ x,
                          float4* __restrict__ out,
                          const float* __restrict__ W,
                          const float* __restrict__ bias) {
    const int tid  = threadIdx.x;
    const int base = blockIdx.x * (TPB * VPT) + tid;
    const bool is_prep = (blockIdx.x < NBINS);

    // 1) Prep blocks: build the table slice FIRST so the W reads are at the
    //    head of this SM's L1tex queue. Block b covers W[b*128 .. b*128+127]
    //    (coalesced). Release via one fence + atomic by tid 0.
    if (is_prep) {
        if (tid < 128) {
            unsigned t  = blockIdx.x * 128u + tid;        // 0..8063
            unsigned d  = t / NBINS;                      // W is [128,63] row-major
            unsigned bn = t - d * NBINS;
            reinterpret_cast<float*>(g_relemb)[bn * D_DIM + d] = W[t] + bias[d];
        }
        __syncthreads();
        if (tid == 0) {
            __threadfence();                              // release block's writes
            atomicAdd(&g_flag, 1);
        }
    }

    // 2) Front-batch the 4 independent DRAM loads (MLP=4). For non-prep
    //    blocks this is the very first thing they do: the 512MB stream
    //    starts immediately and the spin below hides under it.
    float4 xv[VPT];
    #pragma unroll
    for (int k = 0; k < VPT; k++)
        xv[k] = __ldcs(&x[base + k * TPB]);

    // 3) Acquire-spin until all 63 prep blocks signaled.
    if (tid == 0) {
        while (acquire_load(&g_flag) < NBINS) __nanosleep(64);
    }
    __syncthreads();

    // 4) Main stream work: bin is warp-uniform; table read is a coalesced
    //    L1/L2 hit.
    #pragma unroll
    for (int k = 0; k < VPT; k++) {
        int g   = base + k * TPB;
        int d4  = g & 31;
        int row = g >> 5;                         // b*L*L + i*L + j
        int j   = row & (L_DIM - 1);
        int i   = (row >> 9) & (L_DIM - 1);
        int rel = i - j;
        rel = max(-(NBINS / 2), min(NBINS / 2, rel));
        int bin = rel + NBINS / 2;                // 0..62
        float4 rv = g_relemb[bin * 32 + d4];
        float4 ov;
        ov.x = xv[k].x + rv.x;
        ov.y = xv[k].y + rv.y;
        ov.z = xv[k].z + rv.z;
        ov.w = xv[k].w + rv.w;
        __stcs(&out[base + k * TPB], ov);
    }

    // 5) Self-reset so every graph replay starts from flag=0/done=0. All
    //    blocks have passed the spin before done can reach GRID-1, so no
    //    waiter observes the reset.
    __syncthreads();
    if (tid == 0) {
        int d = atomicAdd(&g_done, 1);
        if (d == GRID - 1) {
            g_flag = 0;
            g_done = 0;
            __threadfence();
        }
    }
}

extern "C" void kernel_launch(void* const* d_in, const int* in_sizes, int n_in,
                              void* d_out, int out_size) {
    const float* x    = (const float*)d_in[0];
    const float* W    = (const float*)d_in[2];
    const float* bias = (const float*)d_in[3];
    float* out        = (float*)d_out;

    add_rel_fused_kernel<<<GRID, TPB>>>(
        (const float4*)x, (float4*)out, W, bias);
}